// round 4
// baseline (speedup 1.0000x reference)
#include <cuda_runtime.h>

// out[r] = dot(W1[i1[r]], W2[i2[r]]) + b1[i1[r]] + b2[i2[r]]
// 16 lanes/row (8192 warps = single full wave), 4x LDG.128 per lane,
// L2 evict_last cache-policy on gathers to retain the ~16MB working set
// in L2 across graph replays.

#define BATCH 16384
#define EMBED 128  // 32 float4 per row

__device__ __forceinline__ unsigned long long mk_policy_evict_last() {
    unsigned long long pol;
    asm volatile("createpolicy.fractional.L2::evict_last.b64 %0, 1.0;" : "=l"(pol));
    return pol;
}

__device__ __forceinline__ float4 ldg_el(const float4* p, unsigned long long pol) {
    float4 v;
    asm volatile("ld.global.nc.L2::cache_hint.v4.f32 {%0,%1,%2,%3}, [%4], %5;"
                 : "=f"(v.x), "=f"(v.y), "=f"(v.z), "=f"(v.w)
                 : "l"(p), "l"(pol));
    return v;
}

__device__ __forceinline__ float ldg_el_f(const float* p, unsigned long long pol) {
    float v;
    asm volatile("ld.global.nc.L2::cache_hint.f32 %0, [%1], %2;"
                 : "=f"(v) : "l"(p), "l"(pol));
    return v;
}

__global__ __launch_bounds__(256)
void fused_embed_dot_kernel(const int* __restrict__ i1,
                            const int* __restrict__ i2,
                            const float* __restrict__ W1,
                            const float* __restrict__ W2,
                            const float* __restrict__ b1,
                            const float* __restrict__ b2,
                            float* __restrict__ out) {
    int t   = blockIdx.x * blockDim.x + threadIdx.x;
    int row = t >> 4;        // 16 threads per row
    int sub = t & 15;        // 0..15

    unsigned long long pol = mk_policy_evict_last();

    int idx1 = __ldg(&i1[row]);
    int idx2 = __ldg(&i2[row]);

    // Bias gathers issued early; overlap with row gathers.
    float bv1 = ldg_el_f(&b1[idx1], pol);
    float bv2 = ldg_el_f(&b2[idx2], pol);

    const float4* r1 = reinterpret_cast<const float4*>(W1 + idx1 * EMBED);
    const float4* r2 = reinterpret_cast<const float4*>(W2 + idx2 * EMBED);

    // 4 independent LDG.128 per lane; 16 lanes cover each 512B row.
    float4 a0 = ldg_el(&r1[sub],      pol);
    float4 a1 = ldg_el(&r1[sub + 16], pol);
    float4 c0 = ldg_el(&r2[sub],      pol);
    float4 c1 = ldg_el(&r2[sub + 16], pol);

    float acc0 = a0.x * c0.x;
    float acc1 = a1.x * c1.x;
    acc0 = fmaf(a0.y, c0.y, acc0);  acc1 = fmaf(a1.y, c1.y, acc1);
    acc0 = fmaf(a0.z, c0.z, acc0);  acc1 = fmaf(a1.z, c1.z, acc1);
    acc0 = fmaf(a0.w, c0.w, acc0);  acc1 = fmaf(a1.w, c1.w, acc1);
    float acc = acc0 + acc1;

    // Reduce over 16-lane group.
    acc += __shfl_xor_sync(0xFFFFFFFFu, acc, 1);
    acc += __shfl_xor_sync(0xFFFFFFFFu, acc, 2);
    acc += __shfl_xor_sync(0xFFFFFFFFu, acc, 4);
    acc += __shfl_xor_sync(0xFFFFFFFFu, acc, 8);

    if (sub == 0)
        out[row] = acc + bv1 + bv2;
}

extern "C" void kernel_launch(void* const* d_in, const int* in_sizes, int n_in,
                              void* d_out, int out_size) {
    const int*   i1 = (const int*)d_in[0];
    const int*   i2 = (const int*)d_in[1];
    const float* W1 = (const float*)d_in[2];
    const float* W2 = (const float*)d_in[3];
    const float* b1 = (const float*)d_in[4];
    const float* b2 = (const float*)d_in[5];
    float* out = (float*)d_out;

    // 16384 rows * 16 threads / 256 = 1024 blocks -> 8192 warps, single wave.
    fused_embed_dot_kernel<<<(BATCH * 16) / 256, 256>>>(i1, i2, W1, W2, b1, b2, out);
}